// round 7
// baseline (speedup 1.0000x reference)
#include <cuda_runtime.h>
#include <cuda_bf16.h>

// LoongSpike fractional-SSM Vandermonde kernel, round 5.
// K[h,l] = 2*Re( sum_n C_disc[h,n] * r_n^l ),  r_n = exp(dtA[h,n]).
// Real second-order recurrence x_{l+1} = p x_l + q x_{l-1}, states packed in
// pairs as f32x2. Round-5: states split across 2 blocks (32 each) combined via
// red.global.add into memset-zeroed output -> 2x warps at constant LCc=32;
// seeds stored PRE-PACKED by pair in smem (no mov.b64 packing in phase 2).

#define Hh      512
#define NSTc    32
#define LCc     32      // l-elements per thread/chunk  (DO NOT SHRINK)
#define NCH     64      // chunks per h (block covers all of L=2048)
#define SPB     32      // states per block
#define NPAIRT  16      // packed pairs per block
#define GRPS    4       // 4 groups x 4 pairs
#define NPAIR   4

typedef unsigned long long u64;

#define MUL2(d, a, b) \
    asm("mul.rn.f32x2 %0, %1, %2;" : "=l"(d) : "l"(a), "l"(b))
#define ADD2(d, a, b) \
    asm("add.rn.f32x2 %0, %1, %2;" : "=l"(d) : "l"(a), "l"(b))
#define FMA2(d, a, b, c) \
    asm("fma.rn.f32x2 %0, %1, %2, %3;" : "=l"(d) : "l"(a), "l"(b), "l"(c))
#define UNPACK2(lo, hi, v) \
    asm("mov.b64 {%0, %1}, %2;" : "=r"(lo), "=r"(hi) : "l"(v))
#define REDADD(addr, v) \
    asm volatile("red.global.add.f32 [%0], %1;" :: "l"(addr), "f"(v) : "memory")

__global__ __launch_bounds__(64) void loong_spike_kernel(
    const float* __restrict__ C_real,      // [1, H, NST, 2]
    const float* __restrict__ log_dt,      // [H]
    const float* __restrict__ log_A_real,  // [H, NST]
    const float* __restrict__ A_imag,      // [H, NST]
    const float* __restrict__ omega_logit, // [2]
    const float* __restrict__ eta_logit,   // [2]
    float* __restrict__ out,               // [1, H, L], pre-zeroed
    int L)
{
    // seeds pre-packed by pair: .x = even state, .y = odd state
    __shared__ float2 X0[NPAIRT][NCH + 1];   // x0 seeds
    __shared__ float2 X1[NPAIRT][NCH + 1];   // x1 seeds
    __shared__ float2 Pp[NPAIRT];            // p = 2 Re(r), packed by pair
    __shared__ float2 Qp[NPAIRT];            // q = -|r|^2,  packed by pair

    const int tid  = threadIdx.x;            // 0..63
    const int h    = blockIdx.y;
    const int half = blockIdx.x;             // which 32-state half (== m index)

    // ---------------- Phase 1: one (state, chunk-half) per thread ----------
    {
        const int k     = tid & 31;          // state within half -> nst
        const int pr    = k >> 1;
        const int lane  = k & 1;
        const int rhalf = tid >> 5;          // which 32-chunk range this thread fills
        const int base_ci = rhalf * 32;
        const float l0f = (float)(base_ci * LCc);

        const float dt  = expf(log_dt[h]);
        const float Are = -expf(log_A_real[h * NSTc + k]);
        const float Aim = A_imag[h * NSTc + k];

        const float ol = omega_logit[half];
        const float el = eta_logit[half];
        const float omega = 1e-6f + (1.0f / (1.0f + expf(-ol))) * (100.0f - 1e-6f);
        const float eta   = 1e-6f + (1.0f / (1.0f + expf(-el))) * (10.0f  - 1e-6f);

        const float Afr = -omega + eta * Are;     // A_frac
        const float Afi = eta * Aim;
        const float Cre = eta * C_real[(h * NSTc + k) * 2 + 0];  // C_frac
        const float Cim = eta * C_real[(h * NSTc + k) * 2 + 1];

        const float dr = Afr * dt;                // dtA
        const float di = Afi * dt;

        // r = exp(dtA)
        float er, sn, cs;
        er = expf(dr);
        sincosf(di, &sn, &cs);
        const float rre = er * cs;
        const float rim = er * sn;

        // C_disc
        float Cdre, Cdim;
        const float mag2 = Afr * Afr + Afi * Afi;
        if (mag2 < 1e-12f) {
            Cdre = Cre * dt;
            Cdim = Cim * dt;
        } else {
            const float nre = rre - 1.0f, nim = rim;
            const float tre = Cre * nre - Cim * nim;
            const float tim = Cre * nim + Cim * nre;
            const float dre = Afr + 1e-8f, dim = Afi;
            const float inv = 1.0f / (dre * dre + dim * dim);
            Cdre = (tre * dre + tim * dim) * inv;
            Cdim = (tim * dre - tre * dim) * inv;
        }

        // w at this thread's chunk-range start
        float ssn, scs;
        const float serx = expf(dr * l0f);
        sincosf(di * l0f, &ssn, &scs);
        const float Sre = serx * scs, Sim = serx * ssn;
        float w0re = Cdre * Sre - Cdim * Sim;
        float w0im = Cdre * Sim + Cdim * Sre;

        // per-chunk ratio R = exp(dtA*32); tier ratio R16 = exp(dtA*512)
        float sR, cR, s16, c16;
        const float eR = expf(dr * (float)LCc);
        sincosf(di * (float)LCc, &sR, &cR);
        const float Rre = eR * cR, Rim = eR * sR;
        const float e16 = expf(dr * (float)(16 * LCc));
        sincosf(di * (float)(16 * LCc), &s16, &c16);
        const float R16re = e16 * c16, R16im = e16 * s16;

        if (rhalf == 0) {
            ((float*)&Pp[pr])[lane] = 2.0f * rre;
            ((float*)&Qp[pr])[lane] = -(rre * rre + rim * rim);
        }

        // 16 serial chunk values, then one doubling tier (covers 32 chunks)
        float wr[16], wi[16];
        wr[0] = w0re; wi[0] = w0im;
        #pragma unroll
        for (int i = 1; i < 16; ++i) {
            wr[i] = wr[i-1] * Rre - wi[i-1] * Rim;
            wi[i] = wr[i-1] * Rim + wi[i-1] * Rre;
        }
        #pragma unroll
        for (int tier = 0; tier < 2; ++tier) {
            #pragma unroll
            for (int i = 0; i < 16; ++i) {
                const int ci = base_ci + tier * 16 + i;
                const float x0 = wr[i];
                const float x1 = wr[i] * rre - wi[i] * rim;
                ((float*)&X0[pr][ci])[lane] = x0;
                ((float*)&X1[pr][ci])[lane] = x1;
                if (tier == 0) {
                    const float t1 = wr[i] * R16re - wi[i] * R16im;
                    const float t2 = wr[i] * R16im + wi[i] * R16re;
                    wr[i] = t1; wi[i] = t2;
                }
            }
        }
    }
    __syncthreads();

    // ---------------- Phase 2: packed real second-order recurrence ---------
    const int ci = tid;                      // chunk 0..63
    const int l0 = ci * LCc;
    if (l0 >= L) return;

    u64 acc2[LCc];
    #pragma unroll
    for (int l = 0; l < LCc; ++l) acc2[l] = 0ull;

    #pragma unroll 1
    for (int g = 0; g < GRPS; ++g) {
        u64 prev2[NPAIR], cur2[NPAIR], p2[NPAIR], q2[NPAIR];
        #pragma unroll
        for (int j = 0; j < NPAIR; ++j) {
            const int pr = g * NPAIR + j;
            prev2[j] = *reinterpret_cast<const u64*>(&X0[pr][ci]);
            cur2[j]  = *reinterpret_cast<const u64*>(&X1[pr][ci]);
            p2[j]    = *reinterpret_cast<const u64*>(&Pp[pr]);
            q2[j]    = *reinterpret_cast<const u64*>(&Qp[pr]);
        }
        #pragma unroll
        for (int j = 0; j < NPAIR; ++j)
            ADD2(acc2[0], acc2[0], prev2[j]);
        #pragma unroll
        for (int l = 1; l < LCc; ++l) {
            #pragma unroll
            for (int j = 0; j < NPAIR; ++j) {
                ADD2(acc2[l], acc2[l], cur2[j]);
                u64 t, nx;
                MUL2(t, q2[j], prev2[j]);            // q * x_{l-1}
                FMA2(nx, p2[j], cur2[j], t);         // x_{l+1} = p*x_l + q*x_{l-1}
                prev2[j] = cur2[j];
                cur2[j]  = nx;
            }
        }
    }

    float* op = out + (size_t)h * L + l0;
    const int nl = (l0 + LCc <= L) ? LCc : (L - l0);
    #pragma unroll
    for (int l = 0; l < LCc; ++l) {
        if (l < nl) {
            unsigned int lo, hi;
            UNPACK2(lo, hi, acc2[l]);
            const float v = 2.0f * (__uint_as_float(lo) + __uint_as_float(hi));
            REDADD(op + l, v);
        }
    }
}

extern "C" void kernel_launch(void* const* d_in, const int* in_sizes, int n_in,
                              void* d_out, int out_size) {
    const float* C_real      = (const float*)d_in[0];
    const float* log_dt      = (const float*)d_in[1];
    const float* log_A_real  = (const float*)d_in[2];
    const float* A_imag      = (const float*)d_in[3];
    const float* omega_logit = (const float*)d_in[4];
    const float* eta_logit   = (const float*)d_in[5];
    float* out = (float*)d_out;

    const int L = out_size / Hh;                        // CH == 1

    // zero the output (exactly two deterministic atomic addends land on it)
    cudaMemsetAsync(out, 0, (size_t)out_size * sizeof(float), 0);

    dim3 grid(2, Hh);                                   // 2 state-halves x H
    loong_spike_kernel<<<grid, 64>>>(C_real, log_dt, log_A_real, A_imag,
                                     omega_logit, eta_logit, out, L);
}

// round 8
// speedup vs baseline: 1.5381x; 1.5381x over previous
#include <cuda_runtime.h>
#include <cuda_bf16.h>

// LoongSpike fractional-SSM Vandermonde kernel, round 6.
// K[h,l] = 2*Re( sum_n C_disc[h,n] * r_n^l ),  r_n = exp(dtA[h,n]).
// Real second-order recurrence x_{l+1} = p x_l + q x_{l-1} (p=2Re r, q=-|r|^2),
// states packed in pairs as f32x2.
// Round-6: 64-thread blocks; the 2 warps split the 64 states (32 each) over
// the SAME 32 l-chunks; partial packed accumulators combined in SMEM (no
// global atomics, no memset). Seeds pre-packed by pair in smem (R5's win).

#define Hh      512
#define NSTc    32
#define LCc     32      // l-elements per chunk (do not shrink)
#define CPBc    32      // chunks per block -> block covers 1024 l
#define NSTATES 64
#define NPAIRT  32      // packed pairs total (64 states)
#define GRPS    4       // groups per WARP (4 groups x 4 pairs = 16 pairs)
#define NPAIR   4

typedef unsigned long long u64;

#define MUL2(d, a, b) \
    asm("mul.rn.f32x2 %0, %1, %2;" : "=l"(d) : "l"(a), "l"(b))
#define ADD2(d, a, b) \
    asm("add.rn.f32x2 %0, %1, %2;" : "=l"(d) : "l"(a), "l"(b))
#define FMA2(d, a, b, c) \
    asm("fma.rn.f32x2 %0, %1, %2, %3;" : "=l"(d) : "l"(a), "l"(b), "l"(c))
#define UNPACK2(lo, hi, v) \
    asm("mov.b64 {%0, %1}, %2;" : "=r"(lo), "=r"(hi) : "l"(v))

__global__ __launch_bounds__(64) void loong_spike_kernel(
    const float* __restrict__ C_real,      // [1, H, NST, 2]
    const float* __restrict__ log_dt,      // [H]
    const float* __restrict__ log_A_real,  // [H, NST]
    const float* __restrict__ A_imag,      // [H, NST]
    const float* __restrict__ omega_logit, // [2]
    const float* __restrict__ eta_logit,   // [2]
    float* __restrict__ out,               // [1, H, L]
    int L)
{
    // seeds pre-packed by pair: .x = even state, .y = odd state
    __shared__ float2 X0[NPAIRT][CPBc + 1];   // x0 seeds   (8.4 KB)
    __shared__ float2 X1[NPAIRT][CPBc + 1];   // x1 seeds   (8.4 KB)
    __shared__ float2 Pp[NPAIRT];             // p packed by pair
    __shared__ float2 Qp[NPAIRT];             // q packed by pair
    __shared__ u64    Part[LCc][CPBc];        // warp1 partials (8 KB)

    const int tid = threadIdx.x;              // 0..63
    const int h   = blockIdx.y;
    const int bx  = blockIdx.x;               // which 1024-l half of L
    const int l0_base = bx * (CPBc * LCc);

    // ---------------- Phase 1: one state per thread, 32 chunks each --------
    {
        const int n    = tid;                 // state 0..63
        const int s    = n >> 5;              // m index
        const int nst  = n & 31;
        const int pr   = n >> 1;
        const int lane = n & 1;

        const float dt  = expf(log_dt[h]);
        const float Are = -expf(log_A_real[h * NSTc + nst]);
        const float Aim = A_imag[h * NSTc + nst];

        const float ol = omega_logit[s];
        const float el = eta_logit[s];
        const float omega = 1e-6f + (1.0f / (1.0f + expf(-ol))) * (100.0f - 1e-6f);
        const float eta   = 1e-6f + (1.0f / (1.0f + expf(-el))) * (10.0f  - 1e-6f);

        const float Afr = -omega + eta * Are;     // A_frac
        const float Afi = eta * Aim;
        const float Cre = eta * C_real[(h * NSTc + nst) * 2 + 0];  // C_frac
        const float Cim = eta * C_real[(h * NSTc + nst) * 2 + 1];

        const float dr = Afr * dt;                // dtA
        const float di = Afi * dt;

        // r = exp(dtA)
        float er, sn, cs;
        er = expf(dr);
        sincosf(di, &sn, &cs);
        const float rre = er * cs;
        const float rim = er * sn;

        // C_disc
        float Cdre, Cdim;
        const float mag2 = Afr * Afr + Afi * Afi;
        if (mag2 < 1e-12f) {
            Cdre = Cre * dt;
            Cdim = Cim * dt;
        } else {
            const float nre = rre - 1.0f, nim = rim;
            const float tre = Cre * nre - Cim * nim;
            const float tim = Cre * nim + Cim * nre;
            const float dre = Afr + 1e-8f, dim = Afi;
            const float inv = 1.0f / (dre * dre + dim * dim);
            Cdre = (tre * dre + tim * dim) * inv;
            Cdim = (tim * dre - tre * dim) * inv;
        }

        // w at block start: w = C_disc * exp(dtA * l0_base)
        const float p0 = (float)l0_base;
        float ssn, scs;
        const float serx = expf(dr * p0);
        sincosf(di * p0, &ssn, &scs);
        const float Sre = serx * scs, Sim = serx * ssn;
        const float w0re = Cdre * Sre - Cdim * Sim;
        const float w0im = Cdre * Sim + Cdim * Sre;

        // per-chunk ratio R = exp(dtA*32); tier ratio R16 = exp(dtA*512)
        float sR, cR, s16, c16;
        const float eR = expf(dr * (float)LCc);
        sincosf(di * (float)LCc, &sR, &cR);
        const float Rre = eR * cR, Rim = eR * sR;
        const float e16 = expf(dr * (float)(16 * LCc));
        sincosf(di * (float)(16 * LCc), &s16, &c16);
        const float R16re = e16 * c16, R16im = e16 * s16;

        ((float*)&Pp[pr])[lane] = 2.0f * rre;
        ((float*)&Qp[pr])[lane] = -(rre * rre + rim * rim);

        // 16 serial chunk values, then one doubling tier (covers 32 chunks)
        float wr[16], wi[16];
        wr[0] = w0re; wi[0] = w0im;
        #pragma unroll
        for (int i = 1; i < 16; ++i) {
            wr[i] = wr[i-1] * Rre - wi[i-1] * Rim;
            wi[i] = wr[i-1] * Rim + wi[i-1] * Rre;
        }
        #pragma unroll
        for (int tier = 0; tier < 2; ++tier) {
            #pragma unroll
            for (int i = 0; i < 16; ++i) {
                const int ci = tier * 16 + i;
                const float x0 = wr[i];
                const float x1 = wr[i] * rre - wi[i] * rim;
                ((float*)&X0[pr][ci])[lane] = x0;
                ((float*)&X1[pr][ci])[lane] = x1;
                if (tier == 0) {
                    const float t1 = wr[i] * R16re - wi[i] * R16im;
                    const float t2 = wr[i] * R16im + wi[i] * R16re;
                    wr[i] = t1; wi[i] = t2;
                }
            }
        }
    }
    __syncthreads();

    // ---------------- Phase 2: each warp sweeps 16 pairs over 32 chunks ----
    const int wrp = tid >> 5;                // 0 or 1: which state half
    const int ci  = tid & 31;                // chunk 0..31
    const int l0  = l0_base + ci * LCc;

    u64 acc2[LCc];
    #pragma unroll
    for (int l = 0; l < LCc; ++l) acc2[l] = 0ull;

    const int pr_base = wrp * (GRPS * NPAIR);   // 0 or 16

    #pragma unroll 1
    for (int g = 0; g < GRPS; ++g) {
        u64 prev2[NPAIR], cur2[NPAIR], p2[NPAIR], q2[NPAIR];
        #pragma unroll
        for (int j = 0; j < NPAIR; ++j) {
            const int pr = pr_base + g * NPAIR + j;
            prev2[j] = *reinterpret_cast<const u64*>(&X0[pr][ci]);
            cur2[j]  = *reinterpret_cast<const u64*>(&X1[pr][ci]);
            p2[j]    = *reinterpret_cast<const u64*>(&Pp[pr]);
            q2[j]    = *reinterpret_cast<const u64*>(&Qp[pr]);
        }
        #pragma unroll
        for (int j = 0; j < NPAIR; ++j)
            ADD2(acc2[0], acc2[0], prev2[j]);
        #pragma unroll
        for (int l = 1; l < LCc; ++l) {
            #pragma unroll
            for (int j = 0; j < NPAIR; ++j) {
                ADD2(acc2[l], acc2[l], cur2[j]);
                u64 t, nx;
                MUL2(t, q2[j], prev2[j]);            // q * x_{l-1}
                FMA2(nx, p2[j], cur2[j], t);         // x_{l+1} = p*x_l + q*x_{l-1}
                prev2[j] = cur2[j];
                cur2[j]  = nx;
            }
        }
    }

    // ---------------- Combine in SMEM (warp1 -> warp0), then store ---------
    __syncthreads();           // all phase-2 seed reads complete
    if (wrp == 1) {
        #pragma unroll
        for (int l = 0; l < LCc; ++l)
            Part[l][ci] = acc2[l];                   // transposed, conflict-free
    }
    __syncthreads();

    if (wrp == 0 && l0 < L) {
        float res[LCc];
        #pragma unroll
        for (int l = 0; l < LCc; ++l) {
            u64 c;
            ADD2(c, acc2[l], Part[l][ci]);           // warp0 + warp1 partials
            unsigned int lo, hi;
            UNPACK2(lo, hi, c);
            res[l] = 2.0f * (__uint_as_float(lo) + __uint_as_float(hi));
        }
        float* op = out + (size_t)h * L + l0;
        if (l0 + LCc <= L) {
            #pragma unroll
            for (int l = 0; l < LCc; l += 4) {
                *reinterpret_cast<float4*>(op + l) =
                    make_float4(res[l], res[l + 1], res[l + 2], res[l + 3]);
            }
        } else {
            for (int l = 0; l < LCc && l0 + l < L; ++l) op[l] = res[l];
        }
    }
}

extern "C" void kernel_launch(void* const* d_in, const int* in_sizes, int n_in,
                              void* d_out, int out_size) {
    const float* C_real      = (const float*)d_in[0];
    const float* log_dt      = (const float*)d_in[1];
    const float* log_A_real  = (const float*)d_in[2];
    const float* A_imag      = (const float*)d_in[3];
    const float* omega_logit = (const float*)d_in[4];
    const float* eta_logit   = (const float*)d_in[5];
    float* out = (float*)d_out;

    const int L   = out_size / Hh;                 // CH == 1
    const int lpb = CPBc * LCc;                    // 1024 l per block
    const int gx  = (L + lpb - 1) / lpb;

    dim3 grid(gx, Hh);
    loong_spike_kernel<<<grid, 64>>>(C_real, log_dt, log_A_real, A_imag,
                                     omega_logit, eta_logit, out, L);
}